// round 3
// baseline (speedup 1.0000x reference)
#include <cuda_runtime.h>
#include <cuda_bf16.h>

#define Bdim 64
#define Cdim 64
#define Tdim 128
#define Vdim 25
#define Rdim 8
#define TSdim 9
#define OUTdim 64
#define VV (Vdim*Vdim)          // 625
#define TV (Tdim*Vdim)          // 3200
#define XSTR 136                // T + TS-1 = 136 padded row

// scratch (device globals: no runtime allocation allowed)
__device__ float g_rel[Bdim * Rdim * VV];                 // 1.28 MB
__device__ float g_z[(size_t)Bdim * Cdim * Tdim * Vdim];  // 52.4 MB

// ---------------------------------------------------------------------------
// Kernel A: per-batch prologue.
//   m[c,v]   = mean_t x[b,c,t,v]
//   x1[r,v]  = sum_c W1[r,c]*m[c,v] + b1[r]   (likewise x2)
//   rel[r,i,j] = tanh(x1[r,i] - x2[r,j])  -> g_rel
// ---------------------------------------------------------------------------
__global__ __launch_bounds__(256) void kA(const float* __restrict__ x,
                                          const float* __restrict__ W1,
                                          const float* __restrict__ b1,
                                          const float* __restrict__ W2,
                                          const float* __restrict__ b2) {
    const int b = blockIdx.x;
    const int tid = threadIdx.x;
    __shared__ float W1s[Rdim * Cdim], W2s[Rdim * Cdim];
    __shared__ float ms[Cdim * Vdim];
    __shared__ float x1s[Rdim * Vdim], x2s[Rdim * Vdim];

    for (int i = tid; i < Rdim * Cdim; i += blockDim.x) {
        W1s[i] = W1[i];
        W2s[i] = W2[i];
    }

    const float* xb = x + (size_t)b * Cdim * Tdim * Vdim;
    for (int item = tid; item < Cdim * Vdim; item += blockDim.x) {
        int c = item / Vdim, v = item % Vdim;
        const float* p = xb + (size_t)c * Tdim * Vdim + v;
        float s = 0.f;
#pragma unroll 8
        for (int t = 0; t < Tdim; t++) s += p[t * Vdim];
        ms[item] = s * (1.0f / Tdim);
    }
    __syncthreads();

    for (int item = tid; item < 2 * Rdim * Vdim; item += blockDim.x) {
        int which = item / (Rdim * Vdim);
        int rv = item % (Rdim * Vdim);
        int r = rv / Vdim, v = rv % Vdim;
        const float* Ws = which ? W2s : W1s;
        float s = which ? b2[r] : b1[r];
#pragma unroll
        for (int c = 0; c < Cdim; c++) s += Ws[r * Cdim + c] * ms[c * Vdim + v];
        if (which) x2s[rv] = s; else x1s[rv] = s;
    }
    __syncthreads();

    float* relb = g_rel + (size_t)b * Rdim * VV;
    for (int item = tid; item < Rdim * VV; item += blockDim.x) {
        int r = item / VV;
        int rem = item % VV;
        int i = rem / Vdim, j = rem % Vdim;
        relb[item] = tanhf(x1s[r * Vdim + i] - x2s[r * Vdim + j]);
    }
}

// ---------------------------------------------------------------------------
// Kernel B: per-(b,c) fused dynamic-tap conv.
//   Wk[k][v][i] = b4[c*TS+k] + A[v,i] + sum_r W4[c*TS+k,r]*rel[b,r,v,i]
//   xs[v][tau]  = causally padded x (tau = t + TS-1)
//   z[t,i]      = sum_{v,k} xs[v][t+k] * Wk[k][v][i]
// 400 work items (16 t-groups of 8 x 25 vertices), 416 threads.
// ---------------------------------------------------------------------------
__global__ __launch_bounds__(416) void kB(const float* __restrict__ x,
                                          const float* __restrict__ A,
                                          const float* __restrict__ W4,
                                          const float* __restrict__ b4) {
    const int c = blockIdx.x;
    const int b = blockIdx.y;
    const int tid = threadIdx.x;

    __shared__ float As[VV];                       // 2.5 KB
    __shared__ float Wks[TSdim * VV];              // 22.5 KB
    __shared__ __align__(16) float xs[Vdim * XSTR];// 13.6 KB

    for (int i = tid; i < VV; i += blockDim.x) As[i] = A[i];
    __syncthreads();

    const float* relb = g_rel + (size_t)b * Rdim * VV;
    for (int item = tid; item < TSdim * VV; item += blockDim.x) {
        int k = item / VV, vi = item % VV;
        const float* w4row = W4 + (size_t)(c * TSdim + k) * Rdim;
        float s = b4[c * TSdim + k] + As[vi];
#pragma unroll
        for (int r = 0; r < Rdim; r++) s += w4row[r] * relb[r * VV + vi];
        Wks[item] = s;
    }

    // stage x tile: xs[v][0..7] = 0 (causal pad), xs[v][8+t] = x[b,c,t,v]
    for (int i = tid; i < Vdim * 8; i += blockDim.x)
        xs[(i / 8) * XSTR + (i % 8)] = 0.f;
    const float* xbc = x + ((size_t)b * Cdim + c) * Tdim * Vdim;
    for (int item = tid; item < Tdim * Vdim; item += blockDim.x) {
        int t = item / Vdim, v = item % Vdim;
        xs[v * XSTR + 8 + t] = xbc[item];
    }
    __syncthreads();

    if (tid < 16 * Vdim) {
        const int tg = tid / Vdim;      // 0..15
        const int i  = tid % Vdim;      // 0..24
        const int t0 = tg * 8;
        float acc[8];
#pragma unroll
        for (int tt = 0; tt < 8; tt++) acc[tt] = 0.f;

#pragma unroll 1
        for (int v = 0; v < Vdim; v++) {
            float xv[16];
            const float4* xp4 = reinterpret_cast<const float4*>(&xs[v * XSTR + t0]);
#pragma unroll
            for (int q = 0; q < 4; q++) {
                float4 f = xp4[q];
                xv[4 * q + 0] = f.x; xv[4 * q + 1] = f.y;
                xv[4 * q + 2] = f.z; xv[4 * q + 3] = f.w;
            }
            const float* wkp = &Wks[v * Vdim + i];
#pragma unroll
            for (int k = 0; k < TSdim; k++) {
                float wk = wkp[k * VV];
#pragma unroll
                for (int tt = 0; tt < 8; tt++) acc[tt] += xv[tt + k] * wk;
            }
        }

        float* zbc = g_z + ((size_t)b * Cdim + c) * Tdim * Vdim;
#pragma unroll
        for (int tt = 0; tt < 8; tt++) zbc[(t0 + tt) * Vdim + i] = acc[tt];
    }
}

// ---------------------------------------------------------------------------
// Kernel C: conv3.  out[b,o,t,v] = sum_c W3[o,c]*z[b,c,t,v] + b3[o]
// One thread per (t,v) position, 64 accumulators.
// ---------------------------------------------------------------------------
__global__ __launch_bounds__(256) void kC(const float* __restrict__ W3,
                                          const float* __restrict__ b3,
                                          float* __restrict__ out) {
    const int b = blockIdx.y;
    const int p = blockIdx.x * 256 + threadIdx.x;

    __shared__ __align__(16) float w3t[Cdim * OUTdim]; // [c][o] transposed
    __shared__ float b3s[OUTdim];

    for (int i = threadIdx.x; i < Cdim * OUTdim; i += 256) {
        int c = i / OUTdim, o = i % OUTdim;
        w3t[i] = W3[o * Cdim + c];
    }
    if (threadIdx.x < OUTdim) b3s[threadIdx.x] = b3[threadIdx.x];
    __syncthreads();

    if (p >= TV) return;

    float acc[OUTdim];
#pragma unroll
    for (int o = 0; o < OUTdim; o++) acc[o] = b3s[o];

    const float* zb = g_z + (size_t)b * Cdim * TV + p;
#pragma unroll 8
    for (int c = 0; c < Cdim; c++) {
        float zc = zb[(size_t)c * TV];
        const float4* wp = reinterpret_cast<const float4*>(&w3t[c * OUTdim]);
#pragma unroll
        for (int o4 = 0; o4 < OUTdim / 4; o4++) {
            float4 w = wp[o4];
            acc[4 * o4 + 0] += w.x * zc;
            acc[4 * o4 + 1] += w.y * zc;
            acc[4 * o4 + 2] += w.z * zc;
            acc[4 * o4 + 3] += w.w * zc;
        }
    }

    float* outb = out + (size_t)b * OUTdim * TV + p;
#pragma unroll
    for (int o = 0; o < OUTdim; o++) outb[(size_t)o * TV] = acc[o];
}

// ---------------------------------------------------------------------------
extern "C" void kernel_launch(void* const* d_in, const int* in_sizes, int n_in,
                              void* d_out, int out_size) {
    const float* x  = (const float*)d_in[0];
    const float* A  = (const float*)d_in[1];
    const float* W1 = (const float*)d_in[2];
    const float* b1 = (const float*)d_in[3];
    const float* W2 = (const float*)d_in[4];
    const float* b2 = (const float*)d_in[5];
    const float* W4 = (const float*)d_in[6];
    const float* b4 = (const float*)d_in[7];
    const float* W3 = (const float*)d_in[8];
    const float* b3 = (const float*)d_in[9];
    float* out = (float*)d_out;

    kA<<<Bdim, 256>>>(x, W1, b1, W2, b2);
    kB<<<dim3(Cdim, Bdim), 416>>>(x, A, W4, b4);
    kC<<<dim3((TV + 255) / 256, Bdim), 256>>>(W3, b3, out);
}